// round 17
// baseline (speedup 1.0000x reference)
#include <cuda_runtime.h>
#include <cuda_bf16.h>

// Problem constants
#define NN 4
#define QL 64
#define KL 64
#define DD 768
#define HH 16
#define HD 48
#define EE 300
#define NH (NN*HH)   // 64
#define ESPLIT 5     // e-chunks of 64

typedef unsigned long long ull;

// Packed fp32x2 helpers (SASS FADD2/FFMA2; numerics identical to 2x scalar rn)
#define PK2(d, lo, hi)    asm("mov.b64 %0, {%1, %2};" : "=l"(d) : "f"(lo), "f"(hi))
#define UPK2(lo, hi, s)   asm("mov.b64 {%0, %1}, %2;" : "=f"(lo), "=f"(hi) : "l"(s))
#define FADD2(d, a, b)    asm("add.rn.f32x2 %0, %1, %2;" : "=l"(d) : "l"(a), "l"(b))
#define FFMA2(d, a, b, c) asm("fma.rn.f32x2 %0, %1, %2, %3;" : "=l"(d) : "l"(a), "l"(b), "l"(c))

__device__ __forceinline__ ull relu2(ull p) {
    float x, y; UPK2(x, y, p);
    x = fmaxf(x, 0.f); y = fmaxf(y, 0.f);
    ull r; PK2(r, x, y); return r;
}

// Scratch (device globals — no allocation allowed). 128B-aligned for float4 access.
// Q/K/V hold TWO k-halves (proj k-split); consumers sum halves during staging.
__device__ __align__(128) float g_Q[2*NN*QL*DD];
__device__ __align__(128) float g_K[2*KL*DD];
__device__ __align__(128) float g_V[2*KL*DD];
__device__ __align__(128) float g_Wp[ESPLIT*NH*KL*QL];  // e-partials of [nh][k][q]

// ---------------------------------------------------------------------------
// Kernel 1: fused Q/K/V projections, k-split in 2 halves.
// grid (6 row-tiles, 24 col-tiles, 2 k-halves).
// ---------------------------------------------------------------------------
__global__ __launch_bounds__(256) void proj_kernel(
    const float* __restrict__ qin, const float* __restrict__ kin,
    const float* __restrict__ vin,
    const float* __restrict__ Wq, const float* __restrict__ Wk,
    const float* __restrict__ Wv,
    const float* __restrict__ bq, const float* __restrict__ bk,
    const float* __restrict__ bv,
    float* __restrict__ Qo, float* __restrict__ Ko, float* __restrict__ Vo)
{
    __shared__ float As[32][64];   // [k][m] transposed (256B rows, float4-safe)
    __shared__ float Bs[32][34];   // [k][c] (136B rows, float2-safe)

    const int rt = blockIdx.x;
    const int c0 = blockIdx.y * 32;
    const int ks = blockIdx.z;          // k half
    const int kbase = ks * (DD / 2);
    const float *X, *Wt, *bias;
    float* Y;
    if (rt < 4)      { X = qin + (size_t)rt * 64 * DD; Wt = Wq; bias = bq;
                       Y = Qo + (size_t)ks * NN * QL * DD + (size_t)rt * 64 * DD; }
    else if (rt == 4){ X = kin; Wt = Wk; bias = bk; Y = Ko + (size_t)ks * KL * DD; }
    else             { X = vin; Wt = Wv; bias = bv; Y = Vo + (size_t)ks * KL * DD; }

    const int tid = threadIdx.x;
    const int tx = tid & 15;       // col group (2 cols)
    const int ty = tid >> 4;       // row group (4 rows)
    const int lr = tid >> 2;       // A load row 0..63
    const int lc = (tid & 3) * 4;  // A load k-offset (and +16)
    const int br = tid >> 3;       // B load k-row 0..31
    const int bc = (tid & 7) * 4;  // B load col

    ull accp[2][2] = {{0ull, 0ull}, {0ull, 0ull}};

    for (int k0 = kbase; k0 < kbase + DD / 2; k0 += 32) {
        const float4 a0 = *(const float4*)(X + (size_t)lr * DD + k0 + lc);
        const float4 a1 = *(const float4*)(X + (size_t)lr * DD + k0 + lc + 16);
        const float4 bb = *(const float4*)(Wt + (size_t)(k0 + br) * DD + c0 + bc);
        As[lc + 0][lr] = a0.x; As[lc + 1][lr] = a0.y;
        As[lc + 2][lr] = a0.z; As[lc + 3][lr] = a0.w;
        As[lc + 16][lr] = a1.x; As[lc + 17][lr] = a1.y;
        As[lc + 18][lr] = a1.z; As[lc + 19][lr] = a1.w;
        Bs[br][bc + 0] = bb.x; Bs[br][bc + 1] = bb.y;
        Bs[br][bc + 2] = bb.z; Bs[br][bc + 3] = bb.w;
        __syncthreads();
#pragma unroll
        for (int kk = 0; kk < 32; kk++) {
            const float4 a = *(const float4*)&As[kk][ty * 4];
            const float2 b = *(const float2*)&Bs[kk][tx * 2];
            const ull a01 = ((const ull*)&a)[0];
            const ull a23 = ((const ull*)&a)[1];
            ull bx2, by2; PK2(bx2, b.x, b.x); PK2(by2, b.y, b.y);
            FFMA2(accp[0][0], a01, bx2, accp[0][0]);
            FFMA2(accp[0][1], a23, bx2, accp[0][1]);
            FFMA2(accp[1][0], a01, by2, accp[1][0]);
            FFMA2(accp[1][1], a23, by2, accp[1][1]);
        }
        __syncthreads();
    }

    const float b0 = (ks == 0) ? bias[c0 + tx * 2]     : 0.f;
    const float b1 = (ks == 0) ? bias[c0 + tx * 2 + 1] : 0.f;
    float c00, c10, c20, c30, c01, c11, c21, c31;
    UPK2(c00, c10, accp[0][0]); UPK2(c20, c30, accp[0][1]);
    UPK2(c01, c11, accp[1][0]); UPK2(c21, c31, accp[1][1]);
    float cj0[4] = {c00, c10, c20, c30};
    float cj1[4] = {c01, c11, c21, c31};
#pragma unroll
    for (int i = 0; i < 4; i++) {
        float2 o = make_float2(cj0[i] + b0, cj1[i] + b1);
        *(float2*)(Y + (size_t)(ty * 4 + i) * DD + c0 + tx * 2) = o;
    }
}

// ---------------------------------------------------------------------------
// Kernel 2 (MEGA-FUSED scores+tsum+wk): grid (64 nh, 2 kg, 5 es), 256 thr.
// Per block, entirely in smem:
//   A[64e][64q] = mem_chunk @ Qh^T      (scores task<5, smem output)
//   Bsh[32k][64q] = K_strip @ Qh^T      (scores task=5, smem output)
//   pass1: Tsh[e][k] = sum_q relu(A+B)
//   pass2: Wp[k][q] += relu(A+B)*Tsh
// Dynamic smem 50944B: Ash 16K | Bsh 8.25K | {Ls 12.75K, Qs 12.75K} / Tsh 8K
// ---------------------------------------------------------------------------
#define WK_SMEM 50944
__global__ __launch_bounds__(256) void wkfused_kernel(
    const float* __restrict__ mem, const float* __restrict__ Q,
    const float* __restrict__ K, float* __restrict__ Wp)
{
    extern __shared__ char smraw[];
    float (*Ash)[64] = (float(*)[64])(smraw);            // 64*64*4  = 16384
    float (*Bsh)[66] = (float(*)[66])(smraw + 16384);    // 32*66*4  = 8448
    float (*Ls)[68]  = (float(*)[68])(smraw + 24832);    // 48*68*4  = 13056
    float (*Qs)[68]  = (float(*)[68])(smraw + 37888);    // 48*68*4  = 13056
    float (*Tsh)[32] = (float(*)[32])(smraw + 24832);    // aliases Ls (dead by then)

    const int nh = blockIdx.x;
    const int n = nh >> 4, h = nh & 15;
    const int kg = blockIdx.y;          // 0,1
    const int es = blockIdx.z;          // 0..4
    const int e0 = es * 64;
    const int ec = min(64, EE - e0);    // 64,64,64,64,44

    const int tid = threadIdx.x;
    const int tx = tid & 15;
    const int ty = tid >> 4;

    // ---- Phase 1: stage Qs (full 64 q, sum 2 proj halves) + Ls = mem chunk
    {
        const int r = tid >> 2;         // 0..63
        const int c = tid & 3;
        const float* srcQ0 = Q + (size_t)(n * QL + r) * DD + h * HD;
        const float* srcQ1 = srcQ0 + (size_t)NN * QL * DD;
        const float* srcL = mem + (size_t)(e0 + r) * DD + h * HD;
#pragma unroll
        for (int j = 0; j < 3; j++) {
            const int d0 = c * 4 + j * 16;
            const float4 q0 = *(const float4*)(srcQ0 + d0);
            const float4 q1 = *(const float4*)(srcQ1 + d0);
            Qs[d0 + 0][r] = q0.x + q1.x; Qs[d0 + 1][r] = q0.y + q1.y;
            Qs[d0 + 2][r] = q0.z + q1.z; Qs[d0 + 3][r] = q0.w + q1.w;
            float4 vl = make_float4(0.f, 0.f, 0.f, 0.f);
            if (r < ec) vl = *(const float4*)(srcL + d0);
            Ls[d0 + 0][r] = vl.x; Ls[d0 + 1][r] = vl.y;
            Ls[d0 + 2][r] = vl.z; Ls[d0 + 3][r] = vl.w;
        }
    }
    __syncthreads();

    // ---- Phase 2: A-compute microtile (4e x 4q per thread) -> Ash
    {
        ull accp[4][2];
#pragma unroll
        for (int i = 0; i < 4; i++) { accp[i][0] = 0ull; accp[i][1] = 0ull; }
#pragma unroll 8
        for (int d = 0; d < 48; d++) {
            const float4 a = *(const float4*)&Ls[d][ty * 4];
            const float4 b = *(const float4*)&Qs[d][tx * 4];
            const ull b01 = ((const ull*)&b)[0];
            const ull b23 = ((const ull*)&b)[1];
            ull ax2, ay2, az2, aw2;
            PK2(ax2, a.x, a.x); PK2(ay2, a.y, a.y);
            PK2(az2, a.z, a.z); PK2(aw2, a.w, a.w);
            FFMA2(accp[0][0], b01, ax2, accp[0][0]); FFMA2(accp[0][1], b23, ax2, accp[0][1]);
            FFMA2(accp[1][0], b01, ay2, accp[1][0]); FFMA2(accp[1][1], b23, ay2, accp[1][1]);
            FFMA2(accp[2][0], b01, az2, accp[2][0]); FFMA2(accp[2][1], b23, az2, accp[2][1]);
            FFMA2(accp[3][0], b01, aw2, accp[3][0]); FFMA2(accp[3][1], b23, aw2, accp[3][1]);
        }
#pragma unroll
        for (int i = 0; i < 4; i++) {
            *(ull*)&Ash[ty * 4 + i][tx * 4]     = accp[i][0];
            *(ull*)&Ash[ty * 4 + i][tx * 4 + 2] = accp[i][1];
        }
    }
    __syncthreads();    // Ls free after this

    // ---- Phase 3: stage K strip (32 rows for this kg, sum halves) into Ls
    {
        const int r = tid >> 3;         // 0..31
        const int c = tid & 7;          // 6 d values
        const float* k0p = K + (size_t)(kg * 32 + r) * DD + h * HD + c * 6;
        const float* k1p = k0p + (size_t)KL * DD;
#pragma unroll
        for (int j = 0; j < 3; j++) {
            const float2 a = *(const float2*)(k0p + j * 2);
            const float2 b = *(const float2*)(k1p + j * 2);
            const int d = c * 6 + j * 2;
            Ls[d][r]     = a.x + b.x;
            Ls[d + 1][r] = a.y + b.y;
        }
    }
    __syncthreads();

    // ---- Phase 4: B-compute microtile (2k x 4q per thread) -> Bsh
    {
        ull bacc[2][2];
        bacc[0][0] = bacc[0][1] = bacc[1][0] = bacc[1][1] = 0ull;
#pragma unroll 8
        for (int d = 0; d < 48; d++) {
            const float2 a = *(const float2*)&Ls[d][ty * 2];
            const float4 b = *(const float4*)&Qs[d][tx * 4];
            const ull b01 = ((const ull*)&b)[0];
            const ull b23 = ((const ull*)&b)[1];
            ull ax2, ay2;
            PK2(ax2, a.x, a.x); PK2(ay2, a.y, a.y);
            FFMA2(bacc[0][0], b01, ax2, bacc[0][0]); FFMA2(bacc[0][1], b23, ax2, bacc[0][1]);
            FFMA2(bacc[1][0], b01, ay2, bacc[1][0]); FFMA2(bacc[1][1], b23, ay2, bacc[1][1]);
        }
#pragma unroll
        for (int i = 0; i < 2; i++) {
            *(ull*)&Bsh[ty * 2 + i][tx * 4]     = bacc[i][0];
            *(ull*)&Bsh[ty * 2 + i][tx * 4 + 2] = bacc[i][1];
        }
    }
    __syncthreads();    // Ls/Qs dead; Tsh region usable

    // ---- Phase 5: pass1 — Tsh[e][k] = sum_q relu(A+B)
    {
        const int kp = tid & 31;
        const int eb = tid >> 5;        // e group of 8
        ull tacc2[8];
#pragma unroll
        for (int i = 0; i < 8; i++) tacc2[i] = 0ull;
#pragma unroll 4
        for (int q2 = 0; q2 < 32; q2++) {
            const ull b2 = *(const ull*)&Bsh[kp][q2 * 2];
#pragma unroll
            for (int i = 0; i < 8; i++) {
                const ull a2 = *(const ull*)&Ash[eb * 8 + i][q2 * 2];
                ull p; FADD2(p, a2, b2);
                p = relu2(p);
                FADD2(tacc2[i], tacc2[i], p);
            }
        }
#pragma unroll
        for (int i = 0; i < 8; i++) {
            const int e = eb * 8 + i;
            float x, y; UPK2(x, y, tacc2[i]);
            Tsh[e][kp] = (e < ec) ? (x + y) : 0.f;
        }
    }
    __syncthreads();

    // ---- Phase 6: pass2 — microtile accumulate (2k x 4q per thread)
    {
        const int qx = tx;              // q4 = qx*4
        const int ky = ty;              // local k pair = ky*2, ky*2+1
        const ull b0a = *(const ull*)&Bsh[ky * 2][qx * 4];
        const ull b0b = *(const ull*)&Bsh[ky * 2][qx * 4 + 2];
        const ull b1a = *(const ull*)&Bsh[ky * 2 + 1][qx * 4];
        const ull b1b = *(const ull*)&Bsh[ky * 2 + 1][qx * 4 + 2];

        ull w0a = 0ull, w0b = 0ull, w1a = 0ull, w1b = 0ull;
#pragma unroll 8
        for (int e = 0; e < 64; e++) {
            const float4 a = *(const float4*)&Ash[e][qx * 4];
            const ull a01 = ((const ull*)&a)[0];
            const ull a23 = ((const ull*)&a)[1];
            const float2 t = *(const float2*)&Tsh[e][ky * 2];
            ull tx2, ty2; PK2(tx2, t.x, t.x); PK2(ty2, t.y, t.y);
            ull p;
            FADD2(p, a01, b0a); p = relu2(p); FFMA2(w0a, p, tx2, w0a);
            FADD2(p, a23, b0b); p = relu2(p); FFMA2(w0b, p, tx2, w0b);
            FADD2(p, a01, b1a); p = relu2(p); FFMA2(w1a, p, ty2, w1a);
            FADD2(p, a23, b1b); p = relu2(p); FFMA2(w1b, p, ty2, w1b);
        }

        float4 w0, w1;
        UPK2(w0.x, w0.y, w0a); UPK2(w0.z, w0.w, w0b);
        UPK2(w1.x, w1.y, w1a); UPK2(w1.z, w1.w, w1b);

        float* Wb = Wp + ((size_t)es * NH + nh) * KL * QL + (size_t)kg * 32 * QL;
        *(float4*)(Wb + (size_t)(ky * 2) * QL + qx * 4)     = w0;
        *(float4*)(Wb + (size_t)(ky * 2 + 1) * QL + qx * 4) = w1;
    }
}

// ---------------------------------------------------------------------------
// Kernel 3: out[n,q,h,d] = sum_k (sum_es Wp[es])[nh][k][q] * V[k,h,d]
// grid (64 nh, 4 q-quarters of 16), 256 threads. (R10 shape, measured best)
// ---------------------------------------------------------------------------
__global__ __launch_bounds__(256) void out_kernel(
    const float* __restrict__ Wp, const float* __restrict__ V, float* __restrict__ out)
{
    const int nh = blockIdx.x;
    const int qy = blockIdx.y;          // q quarter
    const int n = nh >> 4, h = nh & 15;
    const int q0 = qy * 16;

    __shared__ float Ws[64][16];   // [k][q-local] (64B rows, float4-safe)
    __shared__ float Vs[64][48];   // [k][d] (192B rows, float4-safe)

    const int tid = threadIdx.x;
    const float* Wb = Wp + (size_t)nh * KL * QL + q0;

    // Ws: 1024 floats = 1 float4/thread, summing ESPLIT partials
    {
        int k = tid >> 2, qq = (tid & 3) * 4;
        const float* p = Wb + (size_t)k * QL + qq;
        float4 s = make_float4(0.f, 0.f, 0.f, 0.f);
#pragma unroll
        for (int es = 0; es < ESPLIT; es++) {
            const float4 v = *(const float4*)(p + (size_t)es * NH * KL * QL);
            s.x += v.x; s.y += v.y; s.z += v.z; s.w += v.w;
        }
        *(float4*)&Ws[k][qq] = s;
    }
    // Vs: 3072 floats = 3 float4/thread, summing 2 k-halves
#pragma unroll
    for (int i = 0; i < 3; i++) {
        int f = tid + i * 256;
        int k = f / 12, d4 = (f % 12) * 4;
        const float* p0 = V + (size_t)k * DD + h * HD + d4;
        const float4 v0 = *(const float4*)p0;
        const float4 v1 = *(const float4*)(p0 + (size_t)KL * DD);
        float4 s = make_float4(v0.x + v1.x, v0.y + v1.y, v0.z + v1.z, v0.w + v1.w);
        *(float4*)&Vs[k][d4] = s;
    }
    __syncthreads();

    const int tx = tid & 15;      // d group of 3
    const int ty = tid >> 4;      // q local (1 each)
    float acc[3] = {0.f, 0.f, 0.f};

#pragma unroll 8
    for (int kk = 0; kk < 64; kk++) {
        const float wq = Ws[kk][ty];
        acc[0] = fmaf(wq, Vs[kk][tx * 3 + 0], acc[0]);
        acc[1] = fmaf(wq, Vs[kk][tx * 3 + 1], acc[1]);
        acc[2] = fmaf(wq, Vs[kk][tx * 3 + 2], acc[2]);
    }

    const int q = q0 + ty;
#pragma unroll
    for (int j = 0; j < 3; j++)
        out[(size_t)(n * QL + q) * DD + h * HD + tx * 3 + j] = acc[j];
}

// ---------------------------------------------------------------------------
// Launch
// Inputs: 0=q 1=k 2=v 3=Wq 4=bq 5=Wk 6=bk 7=Wv 8=bv 9=memory
// ---------------------------------------------------------------------------
extern "C" void kernel_launch(void* const* d_in, const int* in_sizes, int n_in,
                              void* d_out, int out_size)
{
    const float* q   = (const float*)d_in[0];
    const float* k   = (const float*)d_in[1];
    const float* v   = (const float*)d_in[2];
    const float* Wq  = (const float*)d_in[3];
    const float* bq  = (const float*)d_in[4];
    const float* Wk  = (const float*)d_in[5];
    const float* bk  = (const float*)d_in[6];
    const float* Wv  = (const float*)d_in[7];
    const float* bv  = (const float*)d_in[8];
    const float* mem = (const float*)d_in[9];
    float* out = (float*)d_out;

    float *gQ, *gK, *gV, *gWp;
    cudaGetSymbolAddress((void**)&gQ, g_Q);
    cudaGetSymbolAddress((void**)&gK, g_K);
    cudaGetSymbolAddress((void**)&gV, g_V);
    cudaGetSymbolAddress((void**)&gWp, g_Wp);

    // Allow >48KB dynamic smem for the mega-fused kernel (idempotent).
    cudaFuncSetAttribute(wkfused_kernel,
                         cudaFuncAttributeMaxDynamicSharedMemorySize, WK_SMEM);

    // 1. Fused projections, k-split x2 (288 blocks)
    proj_kernel<<<dim3(6, 24, 2), 256>>>(q, k, v, Wq, Wk, Wv, bq, bk, bv, gQ, gK, gV);

    // 2. Mega-fused A/B scores + T + W partials (640 blocks)
    wkfused_kernel<<<dim3(NH, 2, ESPLIT), 256, WK_SMEM>>>(mem, gQ, gK, gWp);

    // 3. out = (sum of W partials)^T @ V_h (256 blocks)
    out_kernel<<<dim3(NH, 4), 256>>>(gWp, gV, out);
}